// round 9
// baseline (speedup 1.0000x reference)
#include <cuda_runtime.h>
#include <cuda_bf16.h>
#include <cstdint>

#define NN   100000
#define EE   1600000
#define NB_SCAN 391   // ceil(NN/256)

// ---------------- scratch (static device globals; no allocation) ----------------
__device__ __align__(16) float g_h[(size_t)NN * 128];     // post-GEMM activations
__device__ __align__(16) float g_agg[(size_t)NN * 128];   // aggregated layer output
__device__ int   g_deg[NN];
__device__ int   g_cur[NN];
__device__ float g_dis[NN];          // (deg+1)^{-1/2}
__device__ int   g_start[NN + 1];    // CSR row offsets
__device__ int   g_part[NB_SCAN];
__device__ int   g_col[EE];          // CSR: source node per edge
__device__ float g_norm[EE];         // CSR: edge weight
__device__ int   g_is64;             // edge_index dtype flag

// ---------------- edge dtype detection ----------------
__global__ void k_dtype(const unsigned long long* __restrict__ ei) {
    __shared__ int bad;
    if (threadIdx.x == 0) bad = 0;
    __syncthreads();
    for (int t = threadIdx.x; t < 4096; t += 256)
        if (ei[t] >> 32) bad = 1;
    __syncthreads();
    if (threadIdx.x == 0) g_is64 = bad ? 0 : 1;
}

__device__ __forceinline__ unsigned edge_val(const void* ei, int pos) {
    if (g_is64) return (unsigned)((const long long*)ei)[pos];
    return (unsigned)((const int*)ei)[pos];
}

// ---------------- graph precompute ----------------
__global__ void k_zero() {
    int i = blockIdx.x * blockDim.x + threadIdx.x;
    if (i < NN) { g_deg[i] = 0; g_cur[i] = 0; }
}

__global__ void k_count(const void* __restrict__ ei) {
    int e = blockIdx.x * blockDim.x + threadIdx.x;
    if (e < EE) {
        unsigned r = edge_val(ei, e);
        if (r < NN) atomicAdd(&g_deg[r], 1);
    }
}

// scan phase 1 + fused dis computation
__global__ void k_scan1() {
    __shared__ int s[256];
    int t = threadIdx.x;
    int i = blockIdx.x * 256 + t;
    int v = (i < NN) ? g_deg[i] : 0;
    if (i < NN) g_dis[i] = rsqrtf((float)v + 1.0f);
    s[t] = v;
    __syncthreads();
#pragma unroll
    for (int off = 1; off < 256; off <<= 1) {
        int x = (t >= off) ? s[t - off] : 0;
        __syncthreads();
        s[t] += x;
        __syncthreads();
    }
    if (i < NN) g_start[i] = s[t] - v;
    if (t == 255) g_part[blockIdx.x] = s[255];
}

__global__ void k_scan2() {
    __shared__ int s[512];
    int t = threadIdx.x;
    int v = (t < NB_SCAN) ? g_part[t] : 0;
    s[t] = v;
    __syncthreads();
#pragma unroll
    for (int off = 1; off < 512; off <<= 1) {
        int x = (t >= off) ? s[t - off] : 0;
        __syncthreads();
        s[t] += x;
        __syncthreads();
    }
    if (t < NB_SCAN) g_part[t] = s[t] - v;
}

__global__ void k_scan3() {
    int i = blockIdx.x * blockDim.x + threadIdx.x;
    if (i < NN) g_start[i] += g_part[i >> 8];
    if (i == 0) g_start[NN] = EE;
}

__global__ void k_place(const void* __restrict__ ei) {
    int e = blockIdx.x * blockDim.x + threadIdx.x;
    if (e < EE) {
        unsigned r = edge_val(ei, e);
        unsigned c = edge_val(ei, EE + e);
        if (r < NN && c < NN) {
            int pos = g_start[r] + atomicAdd(&g_cur[r], 1);
            g_col[pos]  = (int)c;
            g_norm[pos] = g_dis[r] * g_dis[c];
        }
    }
}

// ---------------- split-bf16 HMMA GEMM with ldmatrix ----------------
// g_h[M, Nc] = act(A[M,128]) @ W[128, Nc]
// A = Ah + Al, W = Wh + Wl (bf16 pairs); acc += Ah*Wh + Ah*Wl + Al*Wh (fp32).
// Block: 128m x 64n, 8 warps (4m x 2n), warp tile 32m x 32n.
#define LDA 136   // padded bf16 elems per smem row (272B: 16B-aligned, swizzle-free)

__device__ __forceinline__ uint32_t smem_u32(const void* p) {
    uint32_t a;
    asm("{ .reg .u64 t; cvta.to.shared.u64 t, %1; cvt.u32.u64 %0, t; }" : "=r"(a) : "l"(p));
    return a;
}

__device__ __forceinline__ void mma16816(float* c, const uint32_t* a, const uint32_t* b) {
    asm volatile(
        "mma.sync.aligned.m16n8k16.row.col.f32.bf16.bf16.f32 "
        "{%0,%1,%2,%3}, {%4,%5,%6,%7}, {%8,%9}, {%0,%1,%2,%3};"
        : "+f"(c[0]), "+f"(c[1]), "+f"(c[2]), "+f"(c[3])
        : "r"(a[0]), "r"(a[1]), "r"(a[2]), "r"(a[3]), "r"(b[0]), "r"(b[1]));
}

__device__ __forceinline__ void ldm_x4(uint32_t* r, uint32_t addr) {
    asm volatile("ldmatrix.sync.aligned.m8n8.x4.shared.b16 {%0,%1,%2,%3}, [%4];"
                 : "=r"(r[0]), "=r"(r[1]), "=r"(r[2]), "=r"(r[3]) : "r"(addr));
}

__device__ __forceinline__ uint32_t pack_hi(float a, float b, float* la, float* lb) {
    __nv_bfloat162 h = __floats2bfloat162_rn(a, b);
    *la = a - __bfloat162float(h.x);
    *lb = b - __bfloat162float(h.y);
    uint32_t u; *(__nv_bfloat162*)&u = h; return u;
}
__device__ __forceinline__ uint32_t pack_bf(float a, float b) {
    __nv_bfloat162 h = __floats2bfloat162_rn(a, b);
    uint32_t u; *(__nv_bfloat162*)&u = h; return u;
}

template <bool RELU, bool A_FROM_AGG>
__global__ __launch_bounds__(256) void k_hmma(const float* __restrict__ Aext,
                                              const float* __restrict__ W, int Nc)
{
    extern __shared__ char smem[];
    __nv_bfloat16* Ah = (__nv_bfloat16*)smem;          // [128][LDA]
    __nv_bfloat16* Al = Ah + 128 * LDA;
    __nv_bfloat16* Bh = Al + 128 * LDA;                // [64][LDA]  (W^T: n rows, k cols)
    __nv_bfloat16* Bl = Bh + 64 * LDA;

    const float* A = A_FROM_AGG ? (const float*)g_agg : Aext;
    const int tid  = threadIdx.x;
    const int wid  = tid >> 5;
    const int lane = tid & 31;
    const int m0   = blockIdx.x * 128;
    const int n0   = blockIdx.y * 64;
    const int mrow = (wid & 3) * 32;     // warp m offset in tile
    const int ncol = (wid >> 2) * 32;    // warp n offset in tile

    // ---- stage A: 128x128 fp32 -> bf16 hi/lo (float4 loads, 4B packed stores) ----
    for (int idx = tid; idx < 128 * 32; idx += 256) {
        int row = idx >> 5, c4 = (idx & 31) << 2;
        float4 v = make_float4(0.f, 0.f, 0.f, 0.f);
        if (m0 + row < NN) v = *(const float4*)(A + (size_t)(m0 + row) * 128 + c4);
        if (RELU) {
            v.x = fmaxf(v.x, 0.f); v.y = fmaxf(v.y, 0.f);
            v.z = fmaxf(v.z, 0.f); v.w = fmaxf(v.w, 0.f);
        }
        float lx, ly, lz, lw;
        uint32_t h01 = pack_hi(v.x, v.y, &lx, &ly);
        uint32_t h23 = pack_hi(v.z, v.w, &lz, &lw);
        *(uint32_t*)&Ah[row * LDA + c4]     = h01;
        *(uint32_t*)&Ah[row * LDA + c4 + 2] = h23;
        *(uint32_t*)&Al[row * LDA + c4]     = pack_bf(lx, ly);
        *(uint32_t*)&Al[row * LDA + c4 + 2] = pack_bf(lz, lw);
    }
    // ---- stage B: W^T [64 n][128 k], n >= Nc zero-filled ----
    for (int idx = tid; idx < 64 * 32; idx += 256) {
        int n = idx >> 5, k4 = (idx & 31) << 2;
        float v0 = 0.f, v1 = 0.f, v2 = 0.f, v3 = 0.f;
        if (n0 + n < Nc) {
            v0 = W[(size_t)(k4 + 0) * Nc + n0 + n];
            v1 = W[(size_t)(k4 + 1) * Nc + n0 + n];
            v2 = W[(size_t)(k4 + 2) * Nc + n0 + n];
            v3 = W[(size_t)(k4 + 3) * Nc + n0 + n];
        }
        float l0, l1, l2, l3;
        uint32_t h01 = pack_hi(v0, v1, &l0, &l1);
        uint32_t h23 = pack_hi(v2, v3, &l2, &l3);
        *(uint32_t*)&Bh[n * LDA + k4]     = h01;
        *(uint32_t*)&Bh[n * LDA + k4 + 2] = h23;
        *(uint32_t*)&Bl[n * LDA + k4]     = pack_bf(l0, l1);
        *(uint32_t*)&Bl[n * LDA + k4 + 2] = pack_bf(l2, l3);
    }
    __syncthreads();

    // ---- per-lane ldmatrix element offsets (bf16 units) ----
    // A (m16k16 .x4): lanes 0-7 rows r+0..7 @k0 | 8-15 rows r+8..15 @k0 |
    //                 16-23 rows r+0..7 @k0+8 | 24-31 rows r+8..15 @k0+8
    const int a_off = (mrow + (((lane >> 3) & 1) << 3) + (lane & 7)) * LDA + ((lane >> 4) << 3);
    // B (n16k16 .x4): lanes 0-7 rows n+0..7 @k0 | 8-15 rows n+0..7 @k0+8 |
    //                 16-23 rows n+8..15 @k0 | 24-31 rows n+8..15 @k0+8
    const int b_off = (ncol + ((lane >> 4) << 3) + (lane & 7)) * LDA + (((lane >> 3) & 1) << 3);

    const uint32_t sAh = smem_u32(Ah), sAl = smem_u32(Al);
    const uint32_t sBh = smem_u32(Bh), sBl = smem_u32(Bl);

    float acc[2][4][4];
#pragma unroll
    for (int mt = 0; mt < 2; mt++)
#pragma unroll
        for (int nt = 0; nt < 4; nt++)
#pragma unroll
            for (int r = 0; r < 4; r++) acc[mt][nt][r] = 0.0f;

    // ---- mainloop: 3 products x 8 K-steps into same fp32 accumulators ----
#pragma unroll
    for (int p = 0; p < 3; p++) {
        const uint32_t aBase = (p == 2) ? sAl : sAh;
        const uint32_t bBase = (p == 1) ? sBl : sBh;
#pragma unroll
        for (int kk = 0; kk < 8; kk++) {
            const uint32_t kb = kk * 32;          // 16 bf16 = 32 bytes per K-step
            uint32_t a[2][4], b2[2][4];
            ldm_x4(a[0], aBase + (uint32_t)(a_off * 2) + kb);
            ldm_x4(a[1], aBase + (uint32_t)((a_off + 16 * LDA) * 2) + kb);
            ldm_x4(b2[0], bBase + (uint32_t)(b_off * 2) + kb);
            ldm_x4(b2[1], bBase + (uint32_t)((b_off + 16 * LDA) * 2) + kb);
            // b2[g] = {nt(2g).b0, nt(2g).b1, nt(2g+1).b0, nt(2g+1).b1}
#pragma unroll
            for (int mt = 0; mt < 2; mt++) {
                mma16816(acc[mt][0], a[mt], &b2[0][0]);
                mma16816(acc[mt][1], a[mt], &b2[0][2]);
                mma16816(acc[mt][2], a[mt], &b2[1][0]);
                mma16816(acc[mt][3], a[mt], &b2[1][2]);
            }
        }
    }

    // ---- epilogue: C fragment m16n8: c0=(r,c) c1=(r,c+1) c2=(r+8,c) c3=(r+8,c+1) ----
    const int fr = lane >> 2;
    const int fc = (lane & 3) * 2;
#pragma unroll
    for (int mt = 0; mt < 2; mt++) {
#pragma unroll
        for (int nt = 0; nt < 4; nt++) {
            int m = m0 + mrow + mt * 16 + fr;
            int n = n0 + ncol + nt * 8 + fc;
#pragma unroll
            for (int half = 0; half < 2; half++) {
                int mm = m + half * 8;
                if (mm < NN) {
                    if (n < Nc)     g_h[(size_t)mm * Nc + n]     = acc[mt][nt][half * 2];
                    if (n + 1 < Nc) g_h[(size_t)mm * Nc + n + 1] = acc[mt][nt][half * 2 + 1];
                }
            }
        }
    }
}

// ---------------- aggregation: warp-per-node CSR gather ----------------
__global__ __launch_bounds__(256) void k_agg128(const float* __restrict__ b) {
    int w    = (blockIdx.x * blockDim.x + threadIdx.x) >> 5;
    int lane = threadIdx.x & 31;
    if (w >= NN) return;

    const float4* hv = (const float4*)g_h;
    int   s = g_start[w];
    int   e = g_start[w + 1];
    float d = g_dis[w];
    float dd = d * d;

    float4 acc = hv[(size_t)w * 32 + lane];
    acc.x = dd * acc.x + b[lane * 4 + 0];
    acc.y = dd * acc.y + b[lane * 4 + 1];
    acc.z = dd * acc.z + b[lane * 4 + 2];
    acc.w = dd * acc.w + b[lane * 4 + 3];

    for (int j = s; j < e; j++) {
        unsigned c = (unsigned)g_col[j];
        if (c >= NN) c = 0;
        float wn = g_norm[j];
        float4 v = hv[(size_t)c * 32 + lane];
        acc.x = fmaf(wn, v.x, acc.x);
        acc.y = fmaf(wn, v.y, acc.y);
        acc.z = fmaf(wn, v.z, acc.z);
        acc.w = fmaf(wn, v.w, acc.w);
    }
    ((float4*)g_agg)[(size_t)w * 32 + lane] = acc;
}

__global__ __launch_bounds__(256) void k_agg47(const float* __restrict__ b,
                                               float* __restrict__ out) {
    int w    = (blockIdx.x * blockDim.x + threadIdx.x) >> 5;
    int lane = threadIdx.x & 31;
    if (w >= NN) return;

    int   s = g_start[w];
    int   e = g_start[w + 1];
    float d = g_dis[w];
    float dd = d * d;
    bool  hi = (lane < 15);

    float acc0 = dd * g_h[(size_t)w * 47 + lane] + b[lane];
    float acc1 = hi ? (dd * g_h[(size_t)w * 47 + 32 + lane] + b[32 + lane]) : 0.0f;

    for (int j = s; j < e; j++) {
        unsigned c = (unsigned)g_col[j];
        if (c >= NN) c = 0;
        float wn = g_norm[j];
        acc0 = fmaf(wn, g_h[(size_t)c * 47 + lane], acc0);
        if (hi) acc1 = fmaf(wn, g_h[(size_t)c * 47 + 32 + lane], acc1);
    }
    out[(size_t)w * 47 + lane] = acc0;
    if (hi) out[(size_t)w * 47 + 32 + lane] = acc1;
}

// ---------------- launch ----------------
extern "C" void kernel_launch(void* const* d_in, const int* in_sizes, int n_in,
                              void* d_out, int out_size) {
    // ---- size-driven input identification ----
    const void*  ei = 0;
    const float *x = 0, *W1 = 0, *b1 = 0, *W2 = 0, *b2 = 0, *W3 = 0, *b3 = 0;
    int idx_ei = -1;
    int big[4], nbig = 0;
    int w16[4], nw16 = 0;
    int c128[4], nc128 = 0;
    for (int i = 0; i < n_in; i++) {
        int s = in_sizes[i];
        if (s == 3200000) { idx_ei = i; }
        else if (s == 12800000 && nbig < 4) big[nbig++] = i;
        else if (s == 16384  && nw16 < 4) w16[nw16++] = i;
        else if (s == 128    && nc128 < 4) c128[nc128++] = i;
        else if (s == 6016) W3 = (const float*)d_in[i];
        else if (s == 47)   b3 = (const float*)d_in[i];
    }
    ei = d_in[idx_ei];
    W1 = (const float*)d_in[w16[0]];  W2 = (const float*)d_in[w16[1]];
    b1 = (const float*)d_in[c128[0]]; b2 = (const float*)d_in[c128[1]];
    if (nbig == 2) x = (const float*)((big[0] < idx_ei) ? d_in[big[0]] : d_in[big[1]]);
    else           x = (const float*)d_in[big[0]];

    float* out = (float*)d_out;

    // dynamic smem: (2*128 + 2*64) * LDA * 2 bytes = 104448 (idempotent, not a stream op)
    constexpr int SMEM_GEMM = (2 * 128 + 2 * 64) * LDA * 2;
    cudaFuncSetAttribute(k_hmma<false, false>,
                         cudaFuncAttributeMaxDynamicSharedMemorySize, SMEM_GEMM);
    cudaFuncSetAttribute(k_hmma<true, true>,
                         cudaFuncAttributeMaxDynamicSharedMemorySize, SMEM_GEMM);

    // graph precompute
    k_dtype<<<1, 256>>>((const unsigned long long*)ei);
    k_zero <<<NB_SCAN, 256>>>();
    k_count<<<(EE + 255) / 256, 256>>>(ei);
    k_scan1<<<NB_SCAN, 256>>>();
    k_scan2<<<1, 512>>>();
    k_scan3<<<NB_SCAN, 256>>>();
    k_place<<<(EE + 255) / 256, 256>>>(ei);

    const dim3 gemm128((NN + 127) / 128, 2);   // Nc=128 -> 2 n-tiles
    const dim3 gemm47((NN + 127) / 128, 1);    // Nc=47  -> 1 n-tile
    const int  nb_agg = (NN * 32 + 255) / 256; // warp per node

    // layer 1
    k_hmma<false, false><<<gemm128, 256, SMEM_GEMM>>>(x, W1, 128);
    k_agg128<<<nb_agg, 256>>>(b1);
    // layer 2 (relu fused into A staging)
    k_hmma<true, true><<<gemm128, 256, SMEM_GEMM>>>(nullptr, W2, 128);
    k_agg128<<<nb_agg, 256>>>(b2);
    // layer 3 (47 outputs)
    k_hmma<true, true><<<gemm47, 256, SMEM_GEMM>>>(nullptr, W3, 47);
    k_agg47<<<nb_agg, 256>>>(b3, out);
}

// round 10
// speedup vs baseline: 1.5443x; 1.5443x over previous
#include <cuda_runtime.h>
#include <cuda_fp16.h>
#include <cstdint>

#define NN   100000
#define EE   1600000
#define NB_SCAN 391   // ceil(NN/256)

// ---------------- scratch (static device globals; no allocation) ----------------
__device__ __align__(16) __half g_h16[(size_t)NN * 128];  // post-GEMM activations (fp16)
__device__ __align__(16) float  g_agg[(size_t)NN * 128];  // aggregated layer output (fp32)
__device__ int   g_deg[NN];
__device__ int   g_cur[NN];
__device__ float g_dis[NN];          // (deg+1)^{-1/2}
__device__ int   g_start[NN + 1];    // CSR row offsets
__device__ int   g_part[NB_SCAN];
__device__ int   g_col[EE];          // CSR: source node per edge
__device__ float g_norm[EE];         // CSR: edge weight
__device__ int   g_is64;             // edge_index dtype flag

// ---------------- edge dtype detection ----------------
__global__ void k_dtype(const unsigned long long* __restrict__ ei) {
    __shared__ int bad;
    if (threadIdx.x == 0) bad = 0;
    __syncthreads();
    for (int t = threadIdx.x; t < 4096; t += 256)
        if (ei[t] >> 32) bad = 1;
    __syncthreads();
    if (threadIdx.x == 0) g_is64 = bad ? 0 : 1;
}

__device__ __forceinline__ unsigned edge_val(const void* ei, int pos) {
    if (g_is64) return (unsigned)((const long long*)ei)[pos];
    return (unsigned)((const int*)ei)[pos];
}

// ---------------- graph precompute ----------------
__global__ void k_zero() {
    int i = blockIdx.x * blockDim.x + threadIdx.x;
    if (i < NN) { g_deg[i] = 0; g_cur[i] = 0; }
}

__global__ void k_count(const void* __restrict__ ei) {
    int e = blockIdx.x * blockDim.x + threadIdx.x;
    if (e < EE) {
        unsigned r = edge_val(ei, e);
        if (r < NN) atomicAdd(&g_deg[r], 1);
    }
}

// scan phase 1 + fused dis computation
__global__ void k_scan1() {
    __shared__ int s[256];
    int t = threadIdx.x;
    int i = blockIdx.x * 256 + t;
    int v = (i < NN) ? g_deg[i] : 0;
    if (i < NN) g_dis[i] = rsqrtf((float)v + 1.0f);
    s[t] = v;
    __syncthreads();
#pragma unroll
    for (int off = 1; off < 256; off <<= 1) {
        int x = (t >= off) ? s[t - off] : 0;
        __syncthreads();
        s[t] += x;
        __syncthreads();
    }
    if (i < NN) g_start[i] = s[t] - v;
    if (t == 255) g_part[blockIdx.x] = s[255];
}

__global__ void k_scan2() {
    __shared__ int s[512];
    int t = threadIdx.x;
    int v = (t < NB_SCAN) ? g_part[t] : 0;
    s[t] = v;
    __syncthreads();
#pragma unroll
    for (int off = 1; off < 512; off <<= 1) {
        int x = (t >= off) ? s[t - off] : 0;
        __syncthreads();
        s[t] += x;
        __syncthreads();
    }
    if (t < NB_SCAN) g_part[t] = s[t] - v;
}

__global__ void k_scan3() {
    int i = blockIdx.x * blockDim.x + threadIdx.x;
    if (i < NN) g_start[i] += g_part[i >> 8];
    if (i == 0) g_start[NN] = EE;
}

__global__ void k_place(const void* __restrict__ ei) {
    int e = blockIdx.x * blockDim.x + threadIdx.x;
    if (e < EE) {
        unsigned r = edge_val(ei, e);
        unsigned c = edge_val(ei, EE + e);
        if (r < NN && c < NN) {
            int pos = g_start[r] + atomicAdd(&g_cur[r], 1);
            g_col[pos]  = (int)c;
            g_norm[pos] = g_dis[r] * g_dis[c];
        }
    }
}

// ---------------- fp16 HMMA GEMM with ldmatrix ----------------
// g_h16[M, HS] = fp16( act(A[M,128]) @ W[128, Nc] ), fp32 accumulate.
// Block: 128m x 64n, 8 warps (4m x 2n), warp tile 32m x 32n.
#define LDA 136   // padded fp16 elems per smem row (272B: 16B-aligned, conflict-free)

__device__ __forceinline__ uint32_t smem_u32(const void* p) {
    uint32_t a;
    asm("{ .reg .u64 t; cvta.to.shared.u64 t, %1; cvt.u32.u64 %0, t; }" : "=r"(a) : "l"(p));
    return a;
}

__device__ __forceinline__ void mma16816(float* c, const uint32_t* a, const uint32_t* b) {
    asm volatile(
        "mma.sync.aligned.m16n8k16.row.col.f32.f16.f16.f32 "
        "{%0,%1,%2,%3}, {%4,%5,%6,%7}, {%8,%9}, {%0,%1,%2,%3};"
        : "+f"(c[0]), "+f"(c[1]), "+f"(c[2]), "+f"(c[3])
        : "r"(a[0]), "r"(a[1]), "r"(a[2]), "r"(a[3]), "r"(b[0]), "r"(b[1]));
}

__device__ __forceinline__ void ldm_x4(uint32_t* r, uint32_t addr) {
    asm volatile("ldmatrix.sync.aligned.m8n8.x4.shared.b16 {%0,%1,%2,%3}, [%4];"
                 : "=r"(r[0]), "=r"(r[1]), "=r"(r[2]), "=r"(r[3]) : "r"(addr));
}

// HS: row stride of g_h16 output (128 for hidden layers, 48 for final layer)
template <bool RELU, bool A_FROM_AGG, int HS>
__global__ __launch_bounds__(256) void k_hmma(const float* __restrict__ Aext,
                                              const float* __restrict__ W, int Nc)
{
    extern __shared__ char smem[];
    __half* Ah = (__half*)smem;          // [128][LDA]
    __half* Bh = Ah + 128 * LDA;         // [64][LDA]  (W^T: n rows, k cols)

    const float* A = A_FROM_AGG ? (const float*)g_agg : Aext;
    const int tid  = threadIdx.x;
    const int wid  = tid >> 5;
    const int lane = tid & 31;
    const int m0   = blockIdx.x * 128;
    const int n0   = blockIdx.y * 64;
    const int mrow = (wid & 3) * 32;     // warp m offset in tile
    const int ncol = (wid >> 2) * 32;    // warp n offset in tile

    // ---- stage A: 128x128 fp32 -> fp16 (float4 loads, half2 stores) ----
    for (int idx = tid; idx < 128 * 32; idx += 256) {
        int row = idx >> 5, c4 = (idx & 31) << 2;
        float4 v = make_float4(0.f, 0.f, 0.f, 0.f);
        if (m0 + row < NN) v = *(const float4*)(A + (size_t)(m0 + row) * 128 + c4);
        if (RELU) {
            v.x = fmaxf(v.x, 0.f); v.y = fmaxf(v.y, 0.f);
            v.z = fmaxf(v.z, 0.f); v.w = fmaxf(v.w, 0.f);
        }
        *(__half2*)&Ah[row * LDA + c4]     = __floats2half2_rn(v.x, v.y);
        *(__half2*)&Ah[row * LDA + c4 + 2] = __floats2half2_rn(v.z, v.w);
    }
    // ---- stage B: W^T [64 n][128 k], n >= Nc zero-filled ----
    for (int idx = tid; idx < 64 * 32; idx += 256) {
        int n = idx >> 5, k4 = (idx & 31) << 2;
        float v0 = 0.f, v1 = 0.f, v2 = 0.f, v3 = 0.f;
        if (n0 + n < Nc) {
            v0 = W[(size_t)(k4 + 0) * Nc + n0 + n];
            v1 = W[(size_t)(k4 + 1) * Nc + n0 + n];
            v2 = W[(size_t)(k4 + 2) * Nc + n0 + n];
            v3 = W[(size_t)(k4 + 3) * Nc + n0 + n];
        }
        *(__half2*)&Bh[n * LDA + k4]     = __floats2half2_rn(v0, v1);
        *(__half2*)&Bh[n * LDA + k4 + 2] = __floats2half2_rn(v2, v3);
    }
    __syncthreads();

    // ---- per-lane ldmatrix element offsets (fp16 units) ----
    const int a_off = (mrow + (((lane >> 3) & 1) << 3) + (lane & 7)) * LDA + ((lane >> 4) << 3);
    const int b_off = (ncol + ((lane >> 4) << 3) + (lane & 7)) * LDA + (((lane >> 3) & 1) << 3);

    const uint32_t sAh = smem_u32(Ah);
    const uint32_t sBh = smem_u32(Bh);

    float acc[2][4][4];
#pragma unroll
    for (int mt = 0; mt < 2; mt++)
#pragma unroll
        for (int nt = 0; nt < 4; nt++)
#pragma unroll
            for (int r = 0; r < 4; r++) acc[mt][nt][r] = 0.0f;

    // ---- mainloop: 8 K-steps (K=16 each) ----
#pragma unroll
    for (int kk = 0; kk < 8; kk++) {
        const uint32_t kb = kk * 32;          // 16 fp16 = 32 bytes per K-step
        uint32_t a[2][4], b2[2][4];
        ldm_x4(a[0], sAh + (uint32_t)(a_off * 2) + kb);
        ldm_x4(a[1], sAh + (uint32_t)((a_off + 16 * LDA) * 2) + kb);
        ldm_x4(b2[0], sBh + (uint32_t)(b_off * 2) + kb);
        ldm_x4(b2[1], sBh + (uint32_t)((b_off + 16 * LDA) * 2) + kb);
#pragma unroll
        for (int mt = 0; mt < 2; mt++) {
            mma16816(acc[mt][0], a[mt], &b2[0][0]);
            mma16816(acc[mt][1], a[mt], &b2[0][2]);
            mma16816(acc[mt][2], a[mt], &b2[1][0]);
            mma16816(acc[mt][3], a[mt], &b2[1][2]);
        }
    }

    // ---- epilogue: fp16 output. C frag m16n8: c0=(r,c) c1=(r,c+1) c2=(r+8,c) c3=(r+8,c+1) ----
    const int fr = lane >> 2;
    const int fc = (lane & 3) * 2;
#pragma unroll
    for (int mt = 0; mt < 2; mt++) {
#pragma unroll
        for (int nt = 0; nt < 4; nt++) {
            int m = m0 + mrow + mt * 16 + fr;
            int n = n0 + ncol + nt * 8 + fc;
#pragma unroll
            for (int half = 0; half < 2; half++) {
                int mm = m + half * 8;
                if (mm < NN && n < Nc) {
                    float v0 = acc[mt][nt][half * 2];
                    float v1 = (n + 1 < Nc) ? acc[mt][nt][half * 2 + 1] : 0.0f;
                    *(__half2*)&g_h16[(size_t)mm * HS + n] = __floats2half2_rn(v0, v1);
                }
            }
        }
    }
}

// ---------------- aggregation: warp-per-node CSR gather (fp16 h, fp32 acc) ----------------
__global__ __launch_bounds__(256) void k_agg128(const float* __restrict__ b) {
    int w    = (blockIdx.x * blockDim.x + threadIdx.x) >> 5;
    int lane = threadIdx.x & 31;
    if (w >= NN) return;

    const uint2* hv = (const uint2*)g_h16;    // 8B = 4 channels per lane
    int   s = g_start[w];
    int   e = g_start[w + 1];
    float d = g_dis[w];
    float dd = d * d;

    uint2 raw = hv[(size_t)w * 32 + lane];
    float2 f0 = __half22float2(*(__half2*)&raw.x);
    float2 f1 = __half22float2(*(__half2*)&raw.y);
    float4 acc;
    acc.x = dd * f0.x + b[lane * 4 + 0];
    acc.y = dd * f0.y + b[lane * 4 + 1];
    acc.z = dd * f1.x + b[lane * 4 + 2];
    acc.w = dd * f1.y + b[lane * 4 + 3];

    for (int j = s; j < e; j++) {
        unsigned c = (unsigned)g_col[j];
        if (c >= NN) c = 0;
        float wn = g_norm[j];
        uint2 r2 = hv[(size_t)c * 32 + lane];
        float2 g0 = __half22float2(*(__half2*)&r2.x);
        float2 g1 = __half22float2(*(__half2*)&r2.y);
        acc.x = fmaf(wn, g0.x, acc.x);
        acc.y = fmaf(wn, g0.y, acc.y);
        acc.z = fmaf(wn, g1.x, acc.z);
        acc.w = fmaf(wn, g1.y, acc.w);
    }
    ((float4*)g_agg)[(size_t)w * 32 + lane] = acc;
}

// layer 3: h16 rows are 48 channels (47 real + 1 zero pad)
__global__ __launch_bounds__(256) void k_agg47(const float* __restrict__ b,
                                               float* __restrict__ out) {
    int w    = (blockIdx.x * blockDim.x + threadIdx.x) >> 5;
    int lane = threadIdx.x & 31;
    if (w >= NN || lane >= 24) return;

    const __half2* hv = (const __half2*)g_h16;   // 24 half2 per row
    int   s = g_start[w];
    int   e = g_start[w + 1];
    float d = g_dis[w];
    float dd = d * d;
    int   c0 = lane * 2;
    bool  has1 = (c0 + 1 < 47);

    float2 f = __half22float2(hv[(size_t)w * 24 + lane]);
    float acc0 = dd * f.x + b[c0];
    float acc1 = has1 ? (dd * f.y + b[c0 + 1]) : 0.0f;

    for (int j = s; j < e; j++) {
        unsigned c = (unsigned)g_col[j];
        if (c >= NN) c = 0;
        float wn = g_norm[j];
        float2 g = __half22float2(hv[(size_t)c * 24 + lane]);
        acc0 = fmaf(wn, g.x, acc0);
        acc1 = fmaf(wn, g.y, acc1);
    }
    out[(size_t)w * 47 + c0] = acc0;
    if (has1) out[(size_t)w * 47 + c0 + 1] = acc1;
}

// ---------------- launch ----------------
extern "C" void kernel_launch(void* const* d_in, const int* in_sizes, int n_in,
                              void* d_out, int out_size) {
    // ---- size-driven input identification ----
    const void*  ei = 0;
    const float *x = 0, *W1 = 0, *b1 = 0, *W2 = 0, *b2 = 0, *W3 = 0, *b3 = 0;
    int idx_ei = -1;
    int big[4], nbig = 0;
    int w16[4], nw16 = 0;
    int c128[4], nc128 = 0;
    for (int i = 0; i < n_in; i++) {
        int s = in_sizes[i];
        if (s == 3200000) { idx_ei = i; }
        else if (s == 12800000 && nbig < 4) big[nbig++] = i;
        else if (s == 16384  && nw16 < 4) w16[nw16++] = i;
        else if (s == 128    && nc128 < 4) c128[nc128++] = i;
        else if (s == 6016) W3 = (const float*)d_in[i];
        else if (s == 47)   b3 = (const float*)d_in[i];
    }
    ei = d_in[idx_ei];
    W1 = (const float*)d_in[w16[0]];  W2 = (const float*)d_in[w16[1]];
    b1 = (const float*)d_in[c128[0]]; b2 = (const float*)d_in[c128[1]];
    if (nbig == 2) x = (const float*)((big[0] < idx_ei) ? d_in[big[0]] : d_in[big[1]]);
    else           x = (const float*)d_in[big[0]];

    float* out = (float*)d_out;

    // dynamic smem: (128 + 64) * LDA * 2 bytes = 52224
    constexpr int SMEM_GEMM = (128 + 64) * LDA * 2;
    cudaFuncSetAttribute(k_hmma<false, false, 128>,
                         cudaFuncAttributeMaxDynamicSharedMemorySize, SMEM_GEMM);
    cudaFuncSetAttribute(k_hmma<true, true, 128>,
                         cudaFuncAttributeMaxDynamicSharedMemorySize, SMEM_GEMM);
    cudaFuncSetAttribute(k_hmma<true, true, 48>,
                         cudaFuncAttributeMaxDynamicSharedMemorySize, SMEM_GEMM);

    // graph precompute
    k_dtype<<<1, 256>>>((const unsigned long long*)ei);
    k_zero <<<NB_SCAN, 256>>>();
    k_count<<<(EE + 255) / 256, 256>>>(ei);
    k_scan1<<<NB_SCAN, 256>>>();
    k_scan2<<<1, 512>>>();
    k_scan3<<<NB_SCAN, 256>>>();
    k_place<<<(EE + 255) / 256, 256>>>(ei);

    const dim3 gemm128((NN + 127) / 128, 2);   // Nc=128 -> 2 n-tiles
    const dim3 gemm47((NN + 127) / 128, 1);    // Nc=47  -> 1 n-tile
    const int  nb_agg = (NN * 32 + 255) / 256; // warp per node

    // layer 1
    k_hmma<false, false, 128><<<gemm128, 256, SMEM_GEMM>>>(x, W1, 128);
    k_agg128<<<nb_agg, 256>>>(b1);
    // layer 2 (relu fused into A staging)
    k_hmma<true, true, 128><<<gemm128, 256, SMEM_GEMM>>>(nullptr, W2, 128);
    k_agg128<<<nb_agg, 256>>>(b2);
    // layer 3 (47 outputs, 48-padded fp16 rows)
    k_hmma<true, true, 48><<<gemm47, 256, SMEM_GEMM>>>(nullptr, W3, 47);
    k_agg47<<<nb_agg, 256>>>(b3, out);
}

// round 12
// speedup vs baseline: 1.6183x; 1.0479x over previous
#include <cuda_runtime.h>
#include <cuda_fp16.h>
#include <cstdint>

#define NN   100000
#define EE   1600000
#define NB_SCAN 391   // ceil(NN/256)

// ---------------- scratch (static device globals; no allocation) ----------------
__device__ __align__(16) __half g_h16[(size_t)NN * 128];  // GEMM output (fp16)
__device__ __align__(16) __half g_hin[(size_t)NN * 128];  // agg output, relu'd (fp16)
__device__ int   g_deg[NN];
__device__ int   g_cur[NN];
__device__ float g_dis[NN];          // (deg+1)^{-1/2}
__device__ int   g_start[NN + 1];    // CSR row offsets
__device__ int   g_part[NB_SCAN];
__device__ int   g_col[EE];          // CSR: source node per edge
__device__ float g_norm[EE];         // CSR: edge weight
__device__ int   g_is64;             // edge_index dtype flag

// ---------------- graph precompute ----------------
// zero + dtype detection fused (block 0 detects int64 vs int32 edge_index)
__global__ void k_zero(const unsigned long long* __restrict__ ei) {
    int i = blockIdx.x * blockDim.x + threadIdx.x;
    if (i < NN) { g_deg[i] = 0; g_cur[i] = 0; }
    if (blockIdx.x == 0) {
        __shared__ int bad;
        if (threadIdx.x == 0) bad = 0;
        __syncthreads();
        for (int t = threadIdx.x; t < 4096; t += 256)
            if (ei[t] >> 32) bad = 1;          // benign race
        __syncthreads();
        if (threadIdx.x == 0) g_is64 = bad ? 0 : 1;
    }
}

__device__ __forceinline__ unsigned edge_val(const void* ei, int pos) {
    if (g_is64) return (unsigned)((const long long*)ei)[pos];
    return (unsigned)((const int*)ei)[pos];
}

__global__ void k_count(const void* __restrict__ ei) {
    int e = blockIdx.x * blockDim.x + threadIdx.x;
    if (e < EE) {
        unsigned r = edge_val(ei, e);
        if (r < NN) atomicAdd(&g_deg[r], 1);
    }
}

// scan phase 1 + fused dis computation
__global__ void k_scan1() {
    __shared__ int s[256];
    int t = threadIdx.x;
    int i = blockIdx.x * 256 + t;
    int v = (i < NN) ? g_deg[i] : 0;
    if (i < NN) g_dis[i] = rsqrtf((float)v + 1.0f);
    s[t] = v;
    __syncthreads();
#pragma unroll
    for (int off = 1; off < 256; off <<= 1) {
        int x = (t >= off) ? s[t - off] : 0;
        __syncthreads();
        s[t] += x;
        __syncthreads();
    }
    if (i < NN) g_start[i] = s[t] - v;
    if (t == 255) g_part[blockIdx.x] = s[255];
}

__global__ void k_scan2() {
    __shared__ int s[512];
    int t = threadIdx.x;
    int v = (t < NB_SCAN) ? g_part[t] : 0;
    s[t] = v;
    __syncthreads();
#pragma unroll
    for (int off = 1; off < 512; off <<= 1) {
        int x = (t >= off) ? s[t - off] : 0;
        __syncthreads();
        s[t] += x;
        __syncthreads();
    }
    if (t < NB_SCAN) g_part[t] = s[t] - v;
}

__global__ void k_scan3() {
    int i = blockIdx.x * blockDim.x + threadIdx.x;
    if (i < NN) g_start[i] += g_part[i >> 8];
    if (i == 0) g_start[NN] = EE;
}

__global__ void k_place(const void* __restrict__ ei) {
    int e = blockIdx.x * blockDim.x + threadIdx.x;
    if (e < EE) {
        unsigned r = edge_val(ei, e);
        unsigned c = edge_val(ei, EE + e);
        if (r < NN && c < NN) {
            int pos = g_start[r] + atomicAdd(&g_cur[r], 1);
            g_col[pos]  = (int)c;
            g_norm[pos] = g_dis[r] * g_dis[c];
        }
    }
}

// ---------------- fp16 HMMA GEMM with ldmatrix ----------------
// g_h16[M, HS] = fp16( A[M,128] @ W[128, Nc] ), fp32 accumulate.
// A: fp32 x (layer 1) or fp16 g_hin (layers 2-3, relu pre-applied by agg).
// Block: 128m x BN n, 8 warps (4m x 2n), warp tile 32m x (BN/2)n.
#define LDA 136   // padded fp16 elems per smem row (272B: 16B-aligned, conflict-free)

__device__ __forceinline__ uint32_t smem_u32(const void* p) {
    uint32_t a;
    asm("{ .reg .u64 t; cvta.to.shared.u64 t, %1; cvt.u32.u64 %0, t; }" : "=r"(a) : "l"(p));
    return a;
}

__device__ __forceinline__ void mma16816(float* c, const uint32_t* a, const uint32_t* b) {
    asm volatile(
        "mma.sync.aligned.m16n8k16.row.col.f32.f16.f16.f32 "
        "{%0,%1,%2,%3}, {%4,%5,%6,%7}, {%8,%9}, {%0,%1,%2,%3};"
        : "+f"(c[0]), "+f"(c[1]), "+f"(c[2]), "+f"(c[3])
        : "r"(a[0]), "r"(a[1]), "r"(a[2]), "r"(a[3]), "r"(b[0]), "r"(b[1]));
}

__device__ __forceinline__ void ldm_x4(uint32_t* r, uint32_t addr) {
    asm volatile("ldmatrix.sync.aligned.m8n8.x4.shared.b16 {%0,%1,%2,%3}, [%4];"
                 : "=r"(r[0]), "=r"(r[1]), "=r"(r[2]), "=r"(r[3]) : "r"(addr));
}

// BN: n-tile width (128 or 64). AHALF: A from g_hin (fp16). HS: g_h16 row stride.
template <int BN, bool AHALF, int HS>
__global__ __launch_bounds__(256) void k_hmma(const float* __restrict__ Aext,
                                              const float* __restrict__ W, int Nc)
{
    extern __shared__ char smem[];
    __half* Ah = (__half*)smem;          // [128][LDA]
    __half* Bh = Ah + 128 * LDA;         // [BN][LDA]  (W^T: n rows, k cols)

    constexpr int NT = BN / 16;          // n8-fragments per warp
    const int tid  = threadIdx.x;
    const int wid  = tid >> 5;
    const int lane = tid & 31;
    const int m0   = blockIdx.x * 128;
    const int n0   = blockIdx.y * BN;
    const int mrow = (wid & 3) * 32;         // warp m offset
    const int ncol = (wid >> 2) * (BN / 2);  // warp n offset

    // ---- stage A ----
    if (AHALF) {
        for (int idx = tid; idx < 128 * 16; idx += 256) {       // uint4 = 8 halves
            int row = idx >> 4, c8 = (idx & 15) << 3;
            uint4 v = make_uint4(0, 0, 0, 0);
            if (m0 + row < NN)
                v = *(const uint4*)(g_hin + (size_t)(m0 + row) * 128 + c8);
            *(uint4*)&Ah[row * LDA + c8] = v;
        }
    } else {
        for (int idx = tid; idx < 128 * 32; idx += 256) {       // float4 -> half2 x2
            int row = idx >> 5, c4 = (idx & 31) << 2;
            float4 v = make_float4(0.f, 0.f, 0.f, 0.f);
            if (m0 + row < NN) v = *(const float4*)(Aext + (size_t)(m0 + row) * 128 + c4);
            *(__half2*)&Ah[row * LDA + c4]     = __floats2half2_rn(v.x, v.y);
            *(__half2*)&Ah[row * LDA + c4 + 2] = __floats2half2_rn(v.z, v.w);
        }
    }
    // ---- stage B: W^T [BN n][128 k], n >= Nc zero-filled ----
    for (int idx = tid; idx < BN * 32; idx += 256) {
        int n = idx >> 5, k4 = (idx & 31) << 2;
        float v0 = 0.f, v1 = 0.f, v2 = 0.f, v3 = 0.f;
        if (n0 + n < Nc) {
            v0 = W[(size_t)(k4 + 0) * Nc + n0 + n];
            v1 = W[(size_t)(k4 + 1) * Nc + n0 + n];
            v2 = W[(size_t)(k4 + 2) * Nc + n0 + n];
            v3 = W[(size_t)(k4 + 3) * Nc + n0 + n];
        }
        *(__half2*)&Bh[n * LDA + k4]     = __floats2half2_rn(v0, v1);
        *(__half2*)&Bh[n * LDA + k4 + 2] = __floats2half2_rn(v2, v3);
    }
    __syncthreads();

    // ---- per-lane ldmatrix element offsets (fp16 units) ----
    const int a_off = (mrow + (((lane >> 3) & 1) << 3) + (lane & 7)) * LDA + ((lane >> 4) << 3);
    const int b_off = (ncol + ((lane >> 4) << 3) + (lane & 7)) * LDA + (((lane >> 3) & 1) << 3);

    const uint32_t sAh = smem_u32(Ah);
    const uint32_t sBh = smem_u32(Bh);

    float acc[2][NT][4];
#pragma unroll
    for (int mt = 0; mt < 2; mt++)
#pragma unroll
        for (int nt = 0; nt < NT; nt++)
#pragma unroll
            for (int r = 0; r < 4; r++) acc[mt][nt][r] = 0.0f;

    // ---- mainloop: 8 K-steps (K=16 each) ----
#pragma unroll
    for (int kk = 0; kk < 8; kk++) {
        const uint32_t kb = kk * 32;
        uint32_t a[2][4], b2[NT / 2][4];
        ldm_x4(a[0], sAh + (uint32_t)(a_off * 2) + kb);
        ldm_x4(a[1], sAh + (uint32_t)((a_off + 16 * LDA) * 2) + kb);
#pragma unroll
        for (int g = 0; g < NT / 2; g++)
            ldm_x4(b2[g], sBh + (uint32_t)((b_off + g * 16 * LDA) * 2) + kb);
#pragma unroll
        for (int g = 0; g < NT / 2; g++)
#pragma unroll
            for (int mt = 0; mt < 2; mt++) {
                mma16816(acc[mt][2 * g],     a[mt], &b2[g][0]);
                mma16816(acc[mt][2 * g + 1], a[mt], &b2[g][2]);
            }
    }

    // ---- epilogue: fp16 output ----
    const int fr = lane >> 2;
    const int fc = (lane & 3) * 2;
#pragma unroll
    for (int mt = 0; mt < 2; mt++) {
#pragma unroll
        for (int nt = 0; nt < NT; nt++) {
            int m = m0 + mrow + mt * 16 + fr;
            int n = n0 + ncol + nt * 8 + fc;
#pragma unroll
            for (int half = 0; half < 2; half++) {
                int mm = m + half * 8;
                if (mm < NN && n < Nc) {
                    float v0 = acc[mt][nt][half * 2];
                    float v1 = (n + 1 < Nc) ? acc[mt][nt][half * 2 + 1] : 0.0f;
                    *(__half2*)&g_h16[(size_t)mm * HS + n] = __floats2half2_rn(v0, v1);
                }
            }
        }
    }
}

// ---------------- aggregation: warp-per-node CSR gather (fp16 h, fp32 acc) ----------------
// layers 1-2: out = fp16(relu(dis^2*h + b + sum norm*h[col]))  ->  g_hin
__global__ __launch_bounds__(256) void k_agg128(const float* __restrict__ b) {
    int w    = (blockIdx.x * blockDim.x + threadIdx.x) >> 5;
    int lane = threadIdx.x & 31;
    if (w >= NN) return;

    const uint2* hv = (const uint2*)g_h16;    // 8B = 4 channels per lane
    int   s = g_start[w];
    int   e = g_start[w + 1];
    float d = g_dis[w];
    float dd = d * d;

    uint2 raw = hv[(size_t)w * 32 + lane];
    float2 f0 = __half22float2(*(__half2*)&raw.x);
    float2 f1 = __half22float2(*(__half2*)&raw.y);
    float4 bb = ((const float4*)b)[lane];
    float4 acc;
    acc.x = dd * f0.x + bb.x;
    acc.y = dd * f0.y + bb.y;
    acc.z = dd * f1.x + bb.z;
    acc.w = dd * f1.y + bb.w;

    int j = s;
    for (; j + 1 < e; j += 2) {               // 2-way unroll -> MLP 2
        unsigned c0 = (unsigned)g_col[j];
        unsigned c1 = (unsigned)g_col[j + 1];
        if (c0 >= NN) c0 = 0;
        if (c1 >= NN) c1 = 0;
        float w0 = g_norm[j], w1 = g_norm[j + 1];
        uint2 r0 = hv[(size_t)c0 * 32 + lane];
        uint2 r1 = hv[(size_t)c1 * 32 + lane];
        float2 a0 = __half22float2(*(__half2*)&r0.x);
        float2 a1 = __half22float2(*(__half2*)&r0.y);
        float2 p0 = __half22float2(*(__half2*)&r1.x);
        float2 p1 = __half22float2(*(__half2*)&r1.y);
        acc.x = fmaf(w0, a0.x, acc.x); acc.y = fmaf(w0, a0.y, acc.y);
        acc.z = fmaf(w0, a1.x, acc.z); acc.w = fmaf(w0, a1.y, acc.w);
        acc.x = fmaf(w1, p0.x, acc.x); acc.y = fmaf(w1, p0.y, acc.y);
        acc.z = fmaf(w1, p1.x, acc.z); acc.w = fmaf(w1, p1.y, acc.w);
    }
    if (j < e) {
        unsigned c = (unsigned)g_col[j];
        if (c >= NN) c = 0;
        float wn = g_norm[j];
        uint2 r2 = hv[(size_t)c * 32 + lane];
        float2 g0 = __half22float2(*(__half2*)&r2.x);
        float2 g1 = __half22float2(*(__half2*)&r2.y);
        acc.x = fmaf(wn, g0.x, acc.x); acc.y = fmaf(wn, g0.y, acc.y);
        acc.z = fmaf(wn, g1.x, acc.z); acc.w = fmaf(wn, g1.y, acc.w);
    }
    // relu + fp16 pack
    uint2 outp;
    *(__half2*)&outp.x = __floats2half2_rn(fmaxf(acc.x, 0.f), fmaxf(acc.y, 0.f));
    *(__half2*)&outp.y = __floats2half2_rn(fmaxf(acc.z, 0.f), fmaxf(acc.w, 0.f));
    ((uint2*)g_hin)[(size_t)w * 32 + lane] = outp;
}

// layer 3: h16 rows are 48 channels (47 real + 1 zero pad), fp32 out, no relu
__global__ __launch_bounds__(256) void k_agg47(const float* __restrict__ b,
                                               float* __restrict__ out) {
    int w    = (blockIdx.x * blockDim.x + threadIdx.x) >> 5;
    int lane = threadIdx.x & 31;
    if (w >= NN || lane >= 24) return;

    const __half2* hv = (const __half2*)g_h16;   // 24 half2 per row
    int   s = g_start[w];
    int   e = g_start[w + 1];
    float d = g_dis[w];
    float dd = d * d;
    int   c0 = lane * 2;
    bool  has1 = (c0 + 1 < 47);

    float2 f = __half22float2(hv[(size_t)w * 24 + lane]);
    float acc0 = dd * f.x + b[c0];
    float acc1 = has1 ? (dd * f.y + b[c0 + 1]) : 0.0f;

    int j = s;
    for (; j + 1 < e; j += 2) {
        unsigned cc0 = (unsigned)g_col[j];
        unsigned cc1 = (unsigned)g_col[j + 1];
        if (cc0 >= NN) cc0 = 0;
        if (cc1 >= NN) cc1 = 0;
        float w0 = g_norm[j], w1 = g_norm[j + 1];
        float2 ga = __half22float2(hv[(size_t)cc0 * 24 + lane]);
        float2 gb = __half22float2(hv[(size_t)cc1 * 24 + lane]);
        acc0 = fmaf(w0, ga.x, acc0); acc1 = fmaf(w0, ga.y, acc1);
        acc0 = fmaf(w1, gb.x, acc0); acc1 = fmaf(w1, gb.y, acc1);
    }
    if (j < e) {
        unsigned c = (unsigned)g_col[j];
        if (c >= NN) c = 0;
        float wn = g_norm[j];
        float2 g = __half22float2(hv[(size_t)c * 24 + lane]);
        acc0 = fmaf(wn, g.x, acc0); acc1 = fmaf(wn, g.y, acc1);
    }
    out[(size_t)w * 47 + c0] = acc0;
    if (has1) out[(size_t)w * 47 + c0 + 1] = acc1;
}

// ---------------- launch ----------------
extern "C" void kernel_launch(void* const* d_in, const int* in_sizes, int n_in,
                              void* d_out, int out_size) {
    // ---- size-driven input identification ----
    const void*  ei = 0;
    const float *x = 0, *W1 = 0, *b1 = 0, *W2 = 0, *b2 = 0, *W3 = 0, *b3 = 0;
    int idx_ei = -1;
    int big[4], nbig = 0;
    int w16[4], nw16 = 0;
    int c128[4], nc128 = 0;
    for (int i = 0; i < n_in; i++) {
        int s = in_sizes[i];
        if (s == 3200000) { idx_ei = i; }
        else if (s == 12800000 && nbig < 4) big[nbig++] = i;
        else if (s == 16384  && nw16 < 4) w16[nw16++] = i;
        else if (s == 128    && nc128 < 4) c128[nc128++] = i;
        else if (s == 6016) W3 = (const float*)d_in[i];
        else if (s == 47)   b3 = (const float*)d_in[i];
    }
    ei = d_in[idx_ei];
    W1 = (const float*)d_in[w16[0]];  W2 = (const float*)d_in[w16[1]];
    b1 = (const float*)d_in[c128[0]]; b2 = (const float*)d_in[c128[1]];
    if (nbig == 2) x = (const float*)((big[0] < idx_ei) ? d_in[big[0]] : d_in[big[1]]);
    else           x = (const float*)d_in[big[0]];

    float* out = (float*)d_out;

    // dynamic smem
    constexpr int SMEM128 = (128 + 128) * LDA * 2;   // 69632
    constexpr int SMEM64  = (128 + 64) * LDA * 2;    // 52224
    cudaFuncSetAttribute(k_hmma<128, false, 128>,
                         cudaFuncAttributeMaxDynamicSharedMemorySize, SMEM128);
    cudaFuncSetAttribute(k_hmma<128, true, 128>,
                         cudaFuncAttributeMaxDynamicSharedMemorySize, SMEM128);
    cudaFuncSetAttribute(k_hmma<64, true, 48>,
                         cudaFuncAttributeMaxDynamicSharedMemorySize, SMEM64);

    // graph precompute
    k_zero <<<NB_SCAN, 256>>>((const unsigned long long*)ei);
    k_count<<<(EE + 255) / 256, 256>>>(ei);
    k_scan1<<<NB_SCAN, 256>>>();
    k_scan2<<<1, 512>>>();
    k_scan3<<<NB_SCAN, 256>>>();
    k_place<<<(EE + 255) / 256, 256>>>(ei);

    const int nt = (NN + 127) / 128;           // 782 m-tiles
    const int nb_agg = (NN * 32 + 255) / 256;  // warp per node

    // layer 1 (fp32 x input)
    k_hmma<128, false, 128><<<nt, 256, SMEM128>>>(x, W1, 128);
    k_agg128<<<nb_agg, 256>>>(b1);
    // layer 2 (fp16 g_hin input, relu pre-applied)
    k_hmma<128, true, 128><<<nt, 256, SMEM128>>>(nullptr, W2, 128);
    k_agg128<<<nb_agg, 256>>>(b2);
    // layer 3 (47 outputs, 48-padded fp16 rows)
    k_hmma<64, true, 48><<<nt, 256, SMEM64>>>(nullptr, W3, 47);
    k_agg47<<<nb_agg, 256>>>(b3, out);
}

// round 13
// speedup vs baseline: 1.6797x; 1.0380x over previous
#include <cuda_runtime.h>
#include <cuda_fp16.h>
#include <cstdint>

#define NN   100000
#define EE   1600000
#define NB_SCAN 391   // ceil(NN/256)

// ---------------- scratch (static device globals; no allocation) ----------------
__device__ __align__(16) __half g_h16[(size_t)NN * 128];  // GEMM output (fp16)
__device__ __align__(16) __half g_hin[(size_t)NN * 128];  // agg output, relu'd (fp16)
__device__ int   g_deg[NN];
__device__ int   g_cur[NN];
__device__ float g_dis[NN];          // (deg+1)^{-1/2}
__device__ int   g_start[NN + 1];    // CSR row offsets
__device__ int   g_part[NB_SCAN];
__device__ int   g_col[EE];          // CSR: source node per edge
__device__ float g_norm[EE];         // CSR: edge weight
__device__ int   g_is64;             // edge_index dtype flag

// ---------------- graph precompute ----------------
// zero + dtype detection fused (block 0 detects int64 vs int32 edge_index)
__global__ void k_zero(const unsigned long long* __restrict__ ei) {
    int i = blockIdx.x * blockDim.x + threadIdx.x;
    if (i < NN) { g_deg[i] = 0; g_cur[i] = 0; }
    if (blockIdx.x == 0) {
        __shared__ int bad;
        if (threadIdx.x == 0) bad = 0;
        __syncthreads();
        for (int t = threadIdx.x; t < 4096; t += 256)
            if (ei[t] >> 32) bad = 1;          // benign race
        __syncthreads();
        if (threadIdx.x == 0) g_is64 = bad ? 0 : 1;
    }
}

__device__ __forceinline__ unsigned edge_val(const void* ei, int pos) {
    if (g_is64) return (unsigned)((const long long*)ei)[pos];
    return (unsigned)((const int*)ei)[pos];
}

__global__ void k_count(const void* __restrict__ ei) {
    int e = blockIdx.x * blockDim.x + threadIdx.x;
    if (e < EE) {
        unsigned r = edge_val(ei, e);
        if (r < NN) atomicAdd(&g_deg[r], 1);
    }
}

// scan phase 1 + fused dis computation
__global__ void k_scan1() {
    __shared__ int s[256];
    int t = threadIdx.x;
    int i = blockIdx.x * 256 + t;
    int v = (i < NN) ? g_deg[i] : 0;
    if (i < NN) g_dis[i] = rsqrtf((float)v + 1.0f);
    s[t] = v;
    __syncthreads();
#pragma unroll
    for (int off = 1; off < 256; off <<= 1) {
        int x = (t >= off) ? s[t - off] : 0;
        __syncthreads();
        s[t] += x;
        __syncthreads();
    }
    if (i < NN) g_start[i] = s[t] - v;
    if (t == 255) g_part[blockIdx.x] = s[255];
}

__global__ void k_scan2() {
    __shared__ int s[512];
    int t = threadIdx.x;
    int v = (t < NB_SCAN) ? g_part[t] : 0;
    s[t] = v;
    __syncthreads();
#pragma unroll
    for (int off = 1; off < 512; off <<= 1) {
        int x = (t >= off) ? s[t - off] : 0;
        __syncthreads();
        s[t] += x;
        __syncthreads();
    }
    if (t < NB_SCAN) g_part[t] = s[t] - v;
}

__global__ void k_scan3() {
    int i = blockIdx.x * blockDim.x + threadIdx.x;
    if (i < NN) g_start[i] += g_part[i >> 8];
    if (i == 0) g_start[NN] = EE;
}

__global__ void k_place(const void* __restrict__ ei) {
    int e = blockIdx.x * blockDim.x + threadIdx.x;
    if (e < EE) {
        unsigned r = edge_val(ei, e);
        unsigned c = edge_val(ei, EE + e);
        if (r < NN && c < NN) {
            int pos = g_start[r] + atomicAdd(&g_cur[r], 1);
            g_col[pos]  = (int)c;
            g_norm[pos] = g_dis[r] * g_dis[c];
        }
    }
}

// ---------------- fp16 HMMA GEMM with ldmatrix ----------------
// g_h16[M, HS] = fp16( A[M,128] @ W[128, Nc] ), fp32 accumulate.
// A: fp32 x (layer 1) or fp16 g_hin (layers 2-3, relu pre-applied by agg).
// Block: 128m x BN n, 8 warps (4m x 2n), warp tile 32m x (BN/2)n.
#define LDA 136   // padded fp16 elems per smem row (272B: 16B-aligned, conflict-free)

__device__ __forceinline__ uint32_t smem_u32(const void* p) {
    uint32_t a;
    asm("{ .reg .u64 t; cvta.to.shared.u64 t, %1; cvt.u32.u64 %0, t; }" : "=r"(a) : "l"(p));
    return a;
}

__device__ __forceinline__ void mma16816(float* c, const uint32_t* a, const uint32_t* b) {
    asm volatile(
        "mma.sync.aligned.m16n8k16.row.col.f32.f16.f16.f32 "
        "{%0,%1,%2,%3}, {%4,%5,%6,%7}, {%8,%9}, {%0,%1,%2,%3};"
        : "+f"(c[0]), "+f"(c[1]), "+f"(c[2]), "+f"(c[3])
        : "r"(a[0]), "r"(a[1]), "r"(a[2]), "r"(a[3]), "r"(b[0]), "r"(b[1]));
}

__device__ __forceinline__ void ldm_x4(uint32_t* r, uint32_t addr) {
    asm volatile("ldmatrix.sync.aligned.m8n8.x4.shared.b16 {%0,%1,%2,%3}, [%4];"
                 : "=r"(r[0]), "=r"(r[1]), "=r"(r[2]), "=r"(r[3]) : "r"(addr));
}

// BN: n-tile width (128 or 64). AHALF: A from g_hin (fp16). HS: g_h16 row stride.
template <int BN, bool AHALF, int HS>
__global__ __launch_bounds__(256) void k_hmma(const float* __restrict__ Aext,
                                              const float* __restrict__ W, int Nc)
{
    extern __shared__ char smem[];
    __half* Ah = (__half*)smem;          // [128][LDA]
    __half* Bh = Ah + 128 * LDA;         // [BN][LDA]  (W^T: n rows, k cols)

    constexpr int NT = BN / 16;          // n8-fragments per warp
    const int tid  = threadIdx.x;
    const int wid  = tid >> 5;
    const int lane = tid & 31;
    const int m0   = blockIdx.x * 128;
    const int n0   = blockIdx.y * BN;
    const int mrow = (wid & 3) * 32;         // warp m offset
    const int ncol = (wid >> 2) * (BN / 2);  // warp n offset

    // ---- stage A ----
    if (AHALF) {
        for (int idx = tid; idx < 128 * 16; idx += 256) {       // uint4 = 8 halves
            int row = idx >> 4, c8 = (idx & 15) << 3;
            uint4 v = make_uint4(0, 0, 0, 0);
            if (m0 + row < NN)
                v = *(const uint4*)(g_hin + (size_t)(m0 + row) * 128 + c8);
            *(uint4*)&Ah[row * LDA + c8] = v;
        }
    } else {
        for (int idx = tid; idx < 128 * 32; idx += 256) {       // float4 -> half2 x2
            int row = idx >> 5, c4 = (idx & 31) << 2;
            float4 v = make_float4(0.f, 0.f, 0.f, 0.f);
            if (m0 + row < NN) v = *(const float4*)(Aext + (size_t)(m0 + row) * 128 + c4);
            *(__half2*)&Ah[row * LDA + c4]     = __floats2half2_rn(v.x, v.y);
            *(__half2*)&Ah[row * LDA + c4 + 2] = __floats2half2_rn(v.z, v.w);
        }
    }
    // ---- stage B: W^T [BN n][128 k], n >= Nc zero-filled ----
    for (int idx = tid; idx < BN * 32; idx += 256) {
        int n = idx >> 5, k4 = (idx & 31) << 2;
        float v0 = 0.f, v1 = 0.f, v2 = 0.f, v3 = 0.f;
        if (n0 + n < Nc) {
            v0 = W[(size_t)(k4 + 0) * Nc + n0 + n];
            v1 = W[(size_t)(k4 + 1) * Nc + n0 + n];
            v2 = W[(size_t)(k4 + 2) * Nc + n0 + n];
            v3 = W[(size_t)(k4 + 3) * Nc + n0 + n];
        }
        *(__half2*)&Bh[n * LDA + k4]     = __floats2half2_rn(v0, v1);
        *(__half2*)&Bh[n * LDA + k4 + 2] = __floats2half2_rn(v2, v3);
    }
    __syncthreads();

    // ---- per-lane ldmatrix element offsets (fp16 units) ----
    const int a_off = (mrow + (((lane >> 3) & 1) << 3) + (lane & 7)) * LDA + ((lane >> 4) << 3);
    const int b_off = (ncol + ((lane >> 4) << 3) + (lane & 7)) * LDA + (((lane >> 3) & 1) << 3);

    const uint32_t sAh = smem_u32(Ah);
    const uint32_t sBh = smem_u32(Bh);

    float acc[2][NT][4];
#pragma unroll
    for (int mt = 0; mt < 2; mt++)
#pragma unroll
        for (int nt = 0; nt < NT; nt++)
#pragma unroll
            for (int r = 0; r < 4; r++) acc[mt][nt][r] = 0.0f;

    // ---- mainloop: 8 K-steps (K=16 each) ----
#pragma unroll
    for (int kk = 0; kk < 8; kk++) {
        const uint32_t kb = kk * 32;
        uint32_t a[2][4], b2[NT / 2][4];
        ldm_x4(a[0], sAh + (uint32_t)(a_off * 2) + kb);
        ldm_x4(a[1], sAh + (uint32_t)((a_off + 16 * LDA) * 2) + kb);
#pragma unroll
        for (int g = 0; g < NT / 2; g++)
            ldm_x4(b2[g], sBh + (uint32_t)((b_off + g * 16 * LDA) * 2) + kb);
#pragma unroll
        for (int g = 0; g < NT / 2; g++)
#pragma unroll
            for (int mt = 0; mt < 2; mt++) {
                mma16816(acc[mt][2 * g],     a[mt], &b2[g][0]);
                mma16816(acc[mt][2 * g + 1], a[mt], &b2[g][2]);
            }
    }

    // ---- epilogue: fp16 output ----
    const int fr = lane >> 2;
    const int fc = (lane & 3) * 2;
#pragma unroll
    for (int mt = 0; mt < 2; mt++) {
#pragma unroll
        for (int nt = 0; nt < NT; nt++) {
            int m = m0 + mrow + mt * 16 + fr;
            int n = n0 + ncol + nt * 8 + fc;
#pragma unroll
            for (int half = 0; half < 2; half++) {
                int mm = m + half * 8;
                if (mm < NN && n < Nc) {
                    float v0 = acc[mt][nt][half * 2];
                    float v1 = (n + 1 < Nc) ? acc[mt][nt][half * 2 + 1] : 0.0f;
                    *(__half2*)&g_h16[(size_t)mm * HS + n] = __floats2half2_rn(v0, v1);
                }
            }
        }
    }
}

// ---------------- aggregation: warp-per-node CSR gather (fp16 h, fp32 acc) ----------------
// layers 1-2: out = fp16(relu(dis^2*h + b + sum norm*h[col]))  ->  g_hin
__global__ __launch_bounds__(256) void k_agg128(const float* __restrict__ b) {
    int w    = (blockIdx.x * blockDim.x + threadIdx.x) >> 5;
    int lane = threadIdx.x & 31;
    if (w >= NN) return;

    const uint2* hv = (const uint2*)g_h16;    // 8B = 4 channels per lane
    int   s = g_start[w];
    int   e = g_start[w + 1];
    float d = g_dis[w];
    float dd = d * d;

    uint2 raw = hv[(size_t)w * 32 + lane];
    float2 f0 = __half22float2(*(__half2*)&raw.x);
    float2 f1 = __half22float2(*(__half2*)&raw.y);
    float4 bb = ((const float4*)b)[lane];
    float4 acc;
    acc.x = dd * f0.x + bb.x;
    acc.y = dd * f0.y + bb.y;
    acc.z = dd * f1.x + bb.z;
    acc.w = dd * f1.y + bb.w;

    int j = s;
    for (; j + 1 < e; j += 2) {               // 2-way unroll -> MLP 2
        unsigned c0 = (unsigned)g_col[j];
        unsigned c1 = (unsigned)g_col[j + 1];
        if (c0 >= NN) c0 = 0;
        if (c1 >= NN) c1 = 0;
        float w0 = g_norm[j], w1 = g_norm[j + 1];
        uint2 r0 = hv[(size_t)c0 * 32 + lane];
        uint2 r1 = hv[(size_t)c1 * 32 + lane];
        float2 a0 = __half22float2(*(__half2*)&r0.x);
        float2 a1 = __half22float2(*(__half2*)&r0.y);
        float2 p0 = __half22float2(*(__half2*)&r1.x);
        float2 p1 = __half22float2(*(__half2*)&r1.y);
        acc.x = fmaf(w0, a0.x, acc.x); acc.y = fmaf(w0, a0.y, acc.y);
        acc.z = fmaf(w0, a1.x, acc.z); acc.w = fmaf(w0, a1.y, acc.w);
        acc.x = fmaf(w1, p0.x, acc.x); acc.y = fmaf(w1, p0.y, acc.y);
        acc.z = fmaf(w1, p1.x, acc.z); acc.w = fmaf(w1, p1.y, acc.w);
    }
    if (j < e) {
        unsigned c = (unsigned)g_col[j];
        if (c >= NN) c = 0;
        float wn = g_norm[j];
        uint2 r2 = hv[(size_t)c * 32 + lane];
        float2 g0 = __half22float2(*(__half2*)&r2.x);
        float2 g1 = __half22float2(*(__half2*)&r2.y);
        acc.x = fmaf(wn, g0.x, acc.x); acc.y = fmaf(wn, g0.y, acc.y);
        acc.z = fmaf(wn, g1.x, acc.z); acc.w = fmaf(wn, g1.y, acc.w);
    }
    // relu + fp16 pack
    uint2 outp;
    *(__half2*)&outp.x = __floats2half2_rn(fmaxf(acc.x, 0.f), fmaxf(acc.y, 0.f));
    *(__half2*)&outp.y = __floats2half2_rn(fmaxf(acc.z, 0.f), fmaxf(acc.w, 0.f));
    ((uint2*)g_hin)[(size_t)w * 32 + lane] = outp;
}

// layer 3: h16 rows are 48 channels (47 real + 1 zero pad), fp32 out, no relu
__global__ __launch_bounds__(256) void k_agg47(const float* __restrict__ b,
                                               float* __restrict__ out) {
    int w    = (blockIdx.x * blockDim.x + threadIdx.x) >> 5;
    int lane = threadIdx.x & 31;
    if (w >= NN || lane >= 24) return;

    const __half2* hv = (const __half2*)g_h16;   // 24 half2 per row
    int   s = g_start[w];
    int   e = g_start[w + 1];
    float d = g_dis[w];
    float dd = d * d;
    int   c0 = lane * 2;
    bool  has1 = (c0 + 1 < 47);

    float2 f = __half22float2(hv[(size_t)w * 24 + lane]);
    float acc0 = dd * f.x + b[c0];
    float acc1 = has1 ? (dd * f.y + b[c0 + 1]) : 0.0f;

    int j = s;
    for (; j + 1 < e; j += 2) {
        unsigned cc0 = (unsigned)g_col[j];
        unsigned cc1 = (unsigned)g_col[j + 1];
        if (cc0 >= NN) cc0 = 0;
        if (cc1 >= NN) cc1 = 0;
        float w0 = g_norm[j], w1 = g_norm[j + 1];
        float2 ga = __half22float2(hv[(size_t)cc0 * 24 + lane]);
        float2 gb = __half22float2(hv[(size_t)cc1 * 24 + lane]);
        acc0 = fmaf(w0, ga.x, acc0); acc1 = fmaf(w0, ga.y, acc1);
        acc0 = fmaf(w1, gb.x, acc0); acc1 = fmaf(w1, gb.y, acc1);
    }
    if (j < e) {
        unsigned c = (unsigned)g_col[j];
        if (c >= NN) c = 0;
        float wn = g_norm[j];
        float2 g = __half22float2(hv[(size_t)c * 24 + lane]);
        acc0 = fmaf(wn, g.x, acc0); acc1 = fmaf(wn, g.y, acc1);
    }
    out[(size_t)w * 47 + c0] = acc0;
    if (has1) out[(size_t)w * 47 + c0 + 1] = acc1;
}

// ---------------- launch ----------------
extern "C" void kernel_launch(void* const* d_in, const int* in_sizes, int n_in,
                              void* d_out, int out_size) {
    // ---- size-driven input identification ----
    const void*  ei = 0;
    const float *x = 0, *W1 = 0, *b1 = 0, *W2 = 0, *b2 = 0, *W3 = 0, *b3 = 0;
    int idx_ei = -1;
    int big[4], nbig = 0;
    int w16[4], nw16 = 0;
    int c128[4], nc128 = 0;
    for (int i = 0; i < n_in; i++) {
        int s = in_sizes[i];
        if (s == 3200000) { idx_ei = i; }
        else if (s == 12800000 && nbig < 4) big[nbig++] = i;
        else if (s == 16384  && nw16 < 4) w16[nw16++] = i;
        else if (s == 128    && nc128 < 4) c128[nc128++] = i;
        else if (s == 6016) W3 = (const float*)d_in[i];
        else if (s == 47)   b3 = (const float*)d_in[i];
    }
    ei = d_in[idx_ei];
    W1 = (const float*)d_in[w16[0]];  W2 = (const float*)d_in[w16[1]];
    b1 = (const float*)d_in[c128[0]]; b2 = (const float*)d_in[c128[1]];
    if (nbig == 2) x = (const float*)((big[0] < idx_ei) ? d_in[big[0]] : d_in[big[1]]);
    else           x = (const float*)d_in[big[0]];

    float* out = (float*)d_out;

    // dynamic smem
    constexpr int SMEM128 = (128 + 128) * LDA * 2;   // 69632
    constexpr int SMEM64  = (128 + 64) * LDA * 2;    // 52224
    cudaFuncSetAttribute(k_hmma<128, false, 128>,
                         cudaFuncAttributeMaxDynamicSharedMemorySize, SMEM128);
    cudaFuncSetAttribute(k_hmma<128, true, 128>,
                         cudaFuncAttributeMaxDynamicSharedMemorySize, SMEM128);
    cudaFuncSetAttribute(k_hmma<64, true, 48>,
                         cudaFuncAttributeMaxDynamicSharedMemorySize, SMEM64);

    // side stream + events, created once on first (correctness) call — before capture
    static cudaStream_t s_side = 0;
    static cudaEvent_t  ev_fork = 0, ev_join = 0;
    if (!s_side) {
        cudaStreamCreateWithFlags(&s_side, cudaStreamNonBlocking);
        cudaEventCreateWithFlags(&ev_fork, cudaEventDisableTiming);
        cudaEventCreateWithFlags(&ev_join, cudaEventDisableTiming);
    }

    const int nt = (NN + 127) / 128;           // 782 m-tiles
    const int nb_agg = (NN * 32 + 255) / 256;  // warp per node

    // ---- fork: graph precompute on side stream, GEMM1 on main stream ----
    cudaEventRecord(ev_fork, 0);
    cudaStreamWaitEvent(s_side, ev_fork, 0);

    k_zero <<<NB_SCAN, 256, 0, s_side>>>((const unsigned long long*)ei);
    k_count<<<(EE + 255) / 256, 256, 0, s_side>>>(ei);
    k_scan1<<<NB_SCAN, 256, 0, s_side>>>();
    k_scan2<<<1, 512, 0, s_side>>>();
    k_scan3<<<NB_SCAN, 256, 0, s_side>>>();
    k_place<<<(EE + 255) / 256, 256, 0, s_side>>>(ei);
    cudaEventRecord(ev_join, s_side);

    // layer 1 GEMM (x@W1) — independent of the graph
    k_hmma<128, false, 128><<<nt, 256, SMEM128>>>(x, W1, 128);

    // ---- join: agg needs both GEMM1 output and CSR ----
    cudaStreamWaitEvent(0, ev_join, 0);

    k_agg128<<<nb_agg, 256>>>(b1);
    // layer 2 (fp16 g_hin input, relu pre-applied)
    k_hmma<128, true, 128><<<nt, 256, SMEM128>>>(nullptr, W2, 128);
    k_agg128<<<nb_agg, 256>>>(b2);
    // layer 3 (47 outputs, 48-padded fp16 rows)
    k_hmma<64, true, 48><<<nt, 256, SMEM64>>>(nullptr, W3, 47);
    k_agg47<<<nb_agg, 256>>>(b3, out);
}

// round 14
// speedup vs baseline: 1.7306x; 1.0303x over previous
#include <cuda_runtime.h>
#include <cuda_fp16.h>
#include <cstdint>

#define NN   100000
#define EE   1600000
#define NB_SCAN 391   // ceil(NN/256)

// ---------------- scratch (static device globals; no allocation) ----------------
__device__ __align__(16) __half g_h16[(size_t)NN * 128];  // GEMM output (fp16)
__device__ __align__(16) __half g_hin[(size_t)NN * 128];  // agg output, relu'd (fp16)
__device__ int   g_deg[NN];
__device__ int   g_cur[NN];
__device__ float g_dis[NN];          // (deg+1)^{-1/2}
__device__ int   g_start[NN + 1];    // CSR row offsets
__device__ int   g_part[NB_SCAN];
__device__ int   g_col[EE];          // CSR: source node per edge
__device__ float g_norm[EE];         // CSR: edge weight
__device__ int   g_is64;             // edge_index dtype flag

// ---------------- graph precompute ----------------
// zero + dtype detection fused (block 0 detects int64 vs int32 edge_index)
__global__ void k_zero(const unsigned long long* __restrict__ ei) {
    int i = blockIdx.x * blockDim.x + threadIdx.x;
    if (i < NN) { g_deg[i] = 0; g_cur[i] = 0; }
    if (blockIdx.x == 0) {
        __shared__ int bad;
        if (threadIdx.x == 0) bad = 0;
        __syncthreads();
        for (int t = threadIdx.x; t < 4096; t += 256)
            if (ei[t] >> 32) bad = 1;          // benign race
        __syncthreads();
        if (threadIdx.x == 0) g_is64 = bad ? 0 : 1;
    }
}

__device__ __forceinline__ unsigned edge_val(const void* ei, int pos) {
    if (g_is64) return (unsigned)((const long long*)ei)[pos];
    return (unsigned)((const int*)ei)[pos];
}

__global__ void k_count(const void* __restrict__ ei) {
    int e = blockIdx.x * blockDim.x + threadIdx.x;
    if (e < EE) {
        unsigned r = edge_val(ei, e);
        if (r < NN) atomicAdd(&g_deg[r], 1);
    }
}

// scan phase 1 + fused dis computation
__global__ void k_scan1() {
    __shared__ int s[256];
    int t = threadIdx.x;
    int i = blockIdx.x * 256 + t;
    int v = (i < NN) ? g_deg[i] : 0;
    if (i < NN) g_dis[i] = rsqrtf((float)v + 1.0f);
    s[t] = v;
    __syncthreads();
#pragma unroll
    for (int off = 1; off < 256; off <<= 1) {
        int x = (t >= off) ? s[t - off] : 0;
        __syncthreads();
        s[t] += x;
        __syncthreads();
    }
    if (i < NN) g_start[i] = s[t] - v;
    if (t == 255) g_part[blockIdx.x] = s[255];
}

__global__ void k_scan2() {
    __shared__ int s[512];
    int t = threadIdx.x;
    int v = (t < NB_SCAN) ? g_part[t] : 0;
    s[t] = v;
    __syncthreads();
#pragma unroll
    for (int off = 1; off < 512; off <<= 1) {
        int x = (t >= off) ? s[t - off] : 0;
        __syncthreads();
        s[t] += x;
        __syncthreads();
    }
    if (t < NB_SCAN) g_part[t] = s[t] - v;
}

__global__ void k_scan3() {
    int i = blockIdx.x * blockDim.x + threadIdx.x;
    if (i < NN) g_start[i] += g_part[i >> 8];
    if (i == 0) g_start[NN] = EE;
}

__global__ void k_place(const void* __restrict__ ei) {
    int e = blockIdx.x * blockDim.x + threadIdx.x;
    if (e < EE) {
        unsigned r = edge_val(ei, e);
        unsigned c = edge_val(ei, EE + e);
        if (r < NN && c < NN) {
            int pos = g_start[r] + atomicAdd(&g_cur[r], 1);
            g_col[pos]  = (int)c;
            g_norm[pos] = g_dis[r] * g_dis[c];
        }
    }
}

// ---------------- fp16 HMMA GEMM with ldmatrix ----------------
// g_h16[M, HS] = fp16( A[M,128] @ W[128, Nc] ), fp32 accumulate.
// A: fp32 x (layer 1) or fp16 g_hin (layers 2-3, relu pre-applied by agg).
// Block: 128m x BN n, 8 warps (4m x 2n), warp tile 32m x (BN/2)n.
#define LDA 136   // padded fp16 elems per smem row (272B: 16B-aligned, conflict-free)

__device__ __forceinline__ uint32_t smem_u32(const void* p) {
    uint32_t a;
    asm("{ .reg .u64 t; cvta.to.shared.u64 t, %1; cvt.u32.u64 %0, t; }" : "=r"(a) : "l"(p));
    return a;
}

__device__ __forceinline__ void mma16816(float* c, const uint32_t* a, const uint32_t* b) {
    asm volatile(
        "mma.sync.aligned.m16n8k16.row.col.f32.f16.f16.f32 "
        "{%0,%1,%2,%3}, {%4,%5,%6,%7}, {%8,%9}, {%0,%1,%2,%3};"
        : "+f"(c[0]), "+f"(c[1]), "+f"(c[2]), "+f"(c[3])
        : "r"(a[0]), "r"(a[1]), "r"(a[2]), "r"(a[3]), "r"(b[0]), "r"(b[1]));
}

__device__ __forceinline__ void ldm_x4(uint32_t* r, uint32_t addr) {
    asm volatile("ldmatrix.sync.aligned.m8n8.x4.shared.b16 {%0,%1,%2,%3}, [%4];"
                 : "=r"(r[0]), "=r"(r[1]), "=r"(r[2]), "=r"(r[3]) : "r"(addr));
}

// BN: n-tile width (128 or 64). AHALF: A from g_hin (fp16). HS: g_h16 row stride.
template <int BN, bool AHALF, int HS>
__global__ __launch_bounds__(256) void k_hmma(const float* __restrict__ Aext,
                                              const float* __restrict__ W, int Nc)
{
    extern __shared__ char smem[];
    __half* Ah = (__half*)smem;          // [128][LDA]
    __half* Bh = Ah + 128 * LDA;         // [BN][LDA]  (W^T: n rows, k cols)

    constexpr int NT = BN / 16;          // n8-fragments per warp
    const int tid  = threadIdx.x;
    const int wid  = tid >> 5;
    const int lane = tid & 31;
    const int m0   = blockIdx.x * 128;
    const int n0   = blockIdx.y * BN;
    const int mrow = (wid & 3) * 32;         // warp m offset
    const int ncol = (wid >> 2) * (BN / 2);  // warp n offset

    // ---- stage A ----
    if (AHALF) {
        for (int idx = tid; idx < 128 * 16; idx += 256) {       // uint4 = 8 halves
            int row = idx >> 4, c8 = (idx & 15) << 3;
            uint4 v = make_uint4(0, 0, 0, 0);
            if (m0 + row < NN)
                v = *(const uint4*)(g_hin + (size_t)(m0 + row) * 128 + c8);
            *(uint4*)&Ah[row * LDA + c8] = v;
        }
    } else {
        for (int idx = tid; idx < 128 * 32; idx += 256) {       // float4 -> half2 x2
            int row = idx >> 5, c4 = (idx & 31) << 2;
            float4 v = make_float4(0.f, 0.f, 0.f, 0.f);
            if (m0 + row < NN) v = *(const float4*)(Aext + (size_t)(m0 + row) * 128 + c4);
            *(__half2*)&Ah[row * LDA + c4]     = __floats2half2_rn(v.x, v.y);
            *(__half2*)&Ah[row * LDA + c4 + 2] = __floats2half2_rn(v.z, v.w);
        }
    }
    // ---- stage B: W^T [BN n][128 k], n >= Nc zero-filled ----
    for (int idx = tid; idx < BN * 32; idx += 256) {
        int n = idx >> 5, k4 = (idx & 31) << 2;
        float v0 = 0.f, v1 = 0.f, v2 = 0.f, v3 = 0.f;
        if (n0 + n < Nc) {
            v0 = W[(size_t)(k4 + 0) * Nc + n0 + n];
            v1 = W[(size_t)(k4 + 1) * Nc + n0 + n];
            v2 = W[(size_t)(k4 + 2) * Nc + n0 + n];
            v3 = W[(size_t)(k4 + 3) * Nc + n0 + n];
        }
        *(__half2*)&Bh[n * LDA + k4]     = __floats2half2_rn(v0, v1);
        *(__half2*)&Bh[n * LDA + k4 + 2] = __floats2half2_rn(v2, v3);
    }
    __syncthreads();

    // ---- per-lane ldmatrix element offsets (fp16 units) ----
    const int a_off = (mrow + (((lane >> 3) & 1) << 3) + (lane & 7)) * LDA + ((lane >> 4) << 3);
    const int b_off = (ncol + ((lane >> 4) << 3) + (lane & 7)) * LDA + (((lane >> 3) & 1) << 3);

    const uint32_t sAh = smem_u32(Ah);
    const uint32_t sBh = smem_u32(Bh);

    float acc[2][NT][4];
#pragma unroll
    for (int mt = 0; mt < 2; mt++)
#pragma unroll
        for (int nt = 0; nt < NT; nt++)
#pragma unroll
            for (int r = 0; r < 4; r++) acc[mt][nt][r] = 0.0f;

    // ---- mainloop: 8 K-steps (K=16 each) ----
#pragma unroll
    for (int kk = 0; kk < 8; kk++) {
        const uint32_t kb = kk * 32;
        uint32_t a[2][4], b2[NT / 2][4];
        ldm_x4(a[0], sAh + (uint32_t)(a_off * 2) + kb);
        ldm_x4(a[1], sAh + (uint32_t)((a_off + 16 * LDA) * 2) + kb);
#pragma unroll
        for (int g = 0; g < NT / 2; g++)
            ldm_x4(b2[g], sBh + (uint32_t)((b_off + g * 16 * LDA) * 2) + kb);
#pragma unroll
        for (int g = 0; g < NT / 2; g++)
#pragma unroll
            for (int mt = 0; mt < 2; mt++) {
                mma16816(acc[mt][2 * g],     a[mt], &b2[g][0]);
                mma16816(acc[mt][2 * g + 1], a[mt], &b2[g][2]);
            }
    }

    // ---- epilogue: fp16 output ----
    const int fr = lane >> 2;
    const int fc = (lane & 3) * 2;
#pragma unroll
    for (int mt = 0; mt < 2; mt++) {
#pragma unroll
        for (int nt = 0; nt < NT; nt++) {
            int m = m0 + mrow + mt * 16 + fr;
            int n = n0 + ncol + nt * 8 + fc;
#pragma unroll
            for (int half = 0; half < 2; half++) {
                int mm = m + half * 8;
                if (mm < NN && n < Nc) {
                    float v0 = acc[mt][nt][half * 2];
                    float v1 = (n + 1 < Nc) ? acc[mt][nt][half * 2 + 1] : 0.0f;
                    *(__half2*)&g_h16[(size_t)mm * HS + n] = __floats2half2_rn(v0, v1);
                }
            }
        }
    }
}

// ---------------- aggregation: warp-per-node CSR gather (fp16 h, fp32 acc) ----------------
// layers 1-2: out = fp16(relu(dis^2*h + b + sum norm*h[col]))  ->  g_hin
__global__ __launch_bounds__(256) void k_agg128(const float* __restrict__ b) {
    int w    = (blockIdx.x * blockDim.x + threadIdx.x) >> 5;
    int lane = threadIdx.x & 31;
    if (w >= NN) return;

    const uint2* hv = (const uint2*)g_h16;    // 8B = 4 channels per lane
    int   s = g_start[w];
    int   e = g_start[w + 1];
    float d = g_dis[w];
    float dd = d * d;

    uint2 raw = hv[(size_t)w * 32 + lane];
    float2 f0 = __half22float2(*(__half2*)&raw.x);
    float2 f1 = __half22float2(*(__half2*)&raw.y);
    float4 bb = ((const float4*)b)[lane];
    float4 acc;
    acc.x = dd * f0.x + bb.x;
    acc.y = dd * f0.y + bb.y;
    acc.z = dd * f1.x + bb.z;
    acc.w = dd * f1.y + bb.w;

    int j = s;
    // 4-way unroll -> MLP 4 on the 256B row gathers
    for (; j + 3 < e; j += 4) {
        unsigned c0 = (unsigned)g_col[j],     c1 = (unsigned)g_col[j + 1];
        unsigned c2 = (unsigned)g_col[j + 2], c3 = (unsigned)g_col[j + 3];
        if (c0 >= NN) c0 = 0;
        if (c1 >= NN) c1 = 0;
        if (c2 >= NN) c2 = 0;
        if (c3 >= NN) c3 = 0;
        float w0 = g_norm[j],     w1 = g_norm[j + 1];
        float w2 = g_norm[j + 2], w3 = g_norm[j + 3];
        uint2 r0 = hv[(size_t)c0 * 32 + lane];
        uint2 r1 = hv[(size_t)c1 * 32 + lane];
        uint2 r2 = hv[(size_t)c2 * 32 + lane];
        uint2 r3 = hv[(size_t)c3 * 32 + lane];
        float2 a0 = __half22float2(*(__half2*)&r0.x), a1 = __half22float2(*(__half2*)&r0.y);
        float2 b0 = __half22float2(*(__half2*)&r1.x), b1 = __half22float2(*(__half2*)&r1.y);
        float2 e0 = __half22float2(*(__half2*)&r2.x), e1 = __half22float2(*(__half2*)&r2.y);
        float2 q0 = __half22float2(*(__half2*)&r3.x), q1 = __half22float2(*(__half2*)&r3.y);
        acc.x = fmaf(w0, a0.x, acc.x); acc.y = fmaf(w0, a0.y, acc.y);
        acc.z = fmaf(w0, a1.x, acc.z); acc.w = fmaf(w0, a1.y, acc.w);
        acc.x = fmaf(w1, b0.x, acc.x); acc.y = fmaf(w1, b0.y, acc.y);
        acc.z = fmaf(w1, b1.x, acc.z); acc.w = fmaf(w1, b1.y, acc.w);
        acc.x = fmaf(w2, e0.x, acc.x); acc.y = fmaf(w2, e0.y, acc.y);
        acc.z = fmaf(w2, e1.x, acc.z); acc.w = fmaf(w2, e1.y, acc.w);
        acc.x = fmaf(w3, q0.x, acc.x); acc.y = fmaf(w3, q0.y, acc.y);
        acc.z = fmaf(w3, q1.x, acc.z); acc.w = fmaf(w3, q1.y, acc.w);
    }
    for (; j < e; j++) {
        unsigned c = (unsigned)g_col[j];
        if (c >= NN) c = 0;
        float wn = g_norm[j];
        uint2 r2 = hv[(size_t)c * 32 + lane];
        float2 g0 = __half22float2(*(__half2*)&r2.x);
        float2 g1 = __half22float2(*(__half2*)&r2.y);
        acc.x = fmaf(wn, g0.x, acc.x); acc.y = fmaf(wn, g0.y, acc.y);
        acc.z = fmaf(wn, g1.x, acc.z); acc.w = fmaf(wn, g1.y, acc.w);
    }
    // relu + fp16 pack
    uint2 outp;
    *(__half2*)&outp.x = __floats2half2_rn(fmaxf(acc.x, 0.f), fmaxf(acc.y, 0.f));
    *(__half2*)&outp.y = __floats2half2_rn(fmaxf(acc.z, 0.f), fmaxf(acc.w, 0.f));
    ((uint2*)g_hin)[(size_t)w * 32 + lane] = outp;
}

// layer 3: h16 rows are 48 channels (47 real + 1 zero pad), fp32 out, no relu
__global__ __launch_bounds__(256) void k_agg47(const float* __restrict__ b,
                                               float* __restrict__ out) {
    int w    = (blockIdx.x * blockDim.x + threadIdx.x) >> 5;
    int lane = threadIdx.x & 31;
    if (w >= NN || lane >= 24) return;

    const __half2* hv = (const __half2*)g_h16;   // 24 half2 per row
    int   s = g_start[w];
    int   e = g_start[w + 1];
    float d = g_dis[w];
    float dd = d * d;
    int   c0 = lane * 2;
    bool  has1 = (c0 + 1 < 47);

    float2 f = __half22float2(hv[(size_t)w * 24 + lane]);
    float acc0 = dd * f.x + b[c0];
    float acc1 = has1 ? (dd * f.y + b[c0 + 1]) : 0.0f;

    int j = s;
    for (; j + 3 < e; j += 4) {
        unsigned cc0 = (unsigned)g_col[j],     cc1 = (unsigned)g_col[j + 1];
        unsigned cc2 = (unsigned)g_col[j + 2], cc3 = (unsigned)g_col[j + 3];
        if (cc0 >= NN) cc0 = 0;
        if (cc1 >= NN) cc1 = 0;
        if (cc2 >= NN) cc2 = 0;
        if (cc3 >= NN) cc3 = 0;
        float w0 = g_norm[j],     w1 = g_norm[j + 1];
        float w2 = g_norm[j + 2], w3 = g_norm[j + 3];
        float2 ga = __half22float2(hv[(size_t)cc0 * 24 + lane]);
        float2 gb = __half22float2(hv[(size_t)cc1 * 24 + lane]);
        float2 gc = __half22float2(hv[(size_t)cc2 * 24 + lane]);
        float2 gd = __half22float2(hv[(size_t)cc3 * 24 + lane]);
        acc0 = fmaf(w0, ga.x, acc0); acc1 = fmaf(w0, ga.y, acc1);
        acc0 = fmaf(w1, gb.x, acc0); acc1 = fmaf(w1, gb.y, acc1);
        acc0 = fmaf(w2, gc.x, acc0); acc1 = fmaf(w2, gc.y, acc1);
        acc0 = fmaf(w3, gd.x, acc0); acc1 = fmaf(w3, gd.y, acc1);
    }
    for (; j < e; j++) {
        unsigned c = (unsigned)g_col[j];
        if (c >= NN) c = 0;
        float wn = g_norm[j];
        float2 g = __half22float2(hv[(size_t)c * 24 + lane]);
        acc0 = fmaf(wn, g.x, acc0); acc1 = fmaf(wn, g.y, acc1);
    }
    out[(size_t)w * 47 + c0] = acc0;
    if (has1) out[(size_t)w * 47 + c0 + 1] = acc1;
}

// ---------------- launch ----------------
extern "C" void kernel_launch(void* const* d_in, const int* in_sizes, int n_in,
                              void* d_out, int out_size) {
    // ---- size-driven input identification ----
    const void*  ei = 0;
    const float *x = 0, *W1 = 0, *b1 = 0, *W2 = 0, *b2 = 0, *W3 = 0, *b3 = 0;
    int idx_ei = -1;
    int big[4], nbig = 0;
    int w16[4], nw16 = 0;
    int c128[4], nc128 = 0;
    for (int i = 0; i < n_in; i++) {
        int s = in_sizes[i];
        if (s == 3200000) { idx_ei = i; }
        else if (s == 12800000 && nbig < 4) big[nbig++] = i;
        else if (s == 16384  && nw16 < 4) w16[nw16++] = i;
        else if (s == 128    && nc128 < 4) c128[nc128++] = i;
        else if (s == 6016) W3 = (const float*)d_in[i];
        else if (s == 47)   b3 = (const float*)d_in[i];
    }
    ei = d_in[idx_ei];
    W1 = (const float*)d_in[w16[0]];  W2 = (const float*)d_in[w16[1]];
    b1 = (const float*)d_in[c128[0]]; b2 = (const float*)d_in[c128[1]];
    if (nbig == 2) x = (const float*)((big[0] < idx_ei) ? d_in[big[0]] : d_in[big[1]]);
    else           x = (const float*)d_in[big[0]];

    float* out = (float*)d_out;

    // dynamic smem
    constexpr int SMEM128 = (128 + 128) * LDA * 2;   // 69632
    constexpr int SMEM64  = (128 + 64) * LDA * 2;    // 52224
    cudaFuncSetAttribute(k_hmma<128, false, 128>,
                         cudaFuncAttributeMaxDynamicSharedMemorySize, SMEM128);
    cudaFuncSetAttribute(k_hmma<128, true, 128>,
                         cudaFuncAttributeMaxDynamicSharedMemorySize, SMEM128);
    cudaFuncSetAttribute(k_hmma<64, true, 48>,
                         cudaFuncAttributeMaxDynamicSharedMemorySize, SMEM64);

    // side stream + events, created once on first (correctness) call — before capture
    static cudaStream_t s_side = 0;
    static cudaEvent_t  ev_fork = 0, ev_join = 0;
    if (!s_side) {
        cudaStreamCreateWithFlags(&s_side, cudaStreamNonBlocking);
        cudaEventCreateWithFlags(&ev_fork, cudaEventDisableTiming);
        cudaEventCreateWithFlags(&ev_join, cudaEventDisableTiming);
    }

    const int nt = (NN + 127) / 128;           // 782 m-tiles
    const int nb_agg = (NN * 32 + 255) / 256;  // warp per node

    // ---- fork: graph precompute on side stream, GEMM1 on main stream ----
    // Launch-order note: GEMM1 is deliberately the 4th launch (ncu profiles it).
    cudaEventRecord(ev_fork, 0);
    cudaStreamWaitEvent(s_side, ev_fork, 0);

    k_zero <<<NB_SCAN, 256, 0, s_side>>>((const unsigned long long*)ei);   // 1
    k_count<<<(EE + 255) / 256, 256, 0, s_side>>>(ei);                     // 2
    k_scan1<<<NB_SCAN, 256, 0, s_side>>>();                                // 3

    // layer 1 GEMM (x@W1) — independent of the graph                      // 4
    k_hmma<128, false, 128><<<nt, 256, SMEM128>>>(x, W1, 128);

    k_scan2<<<1, 512, 0, s_side>>>();                                      // 5
    k_scan3<<<NB_SCAN, 256, 0, s_side>>>();                                // 6
    k_place<<<(EE + 255) / 256, 256, 0, s_side>>>(ei);                     // 7
    cudaEventRecord(ev_join, s_side);

    // ---- join: agg needs both GEMM1 output and CSR ----
    cudaStreamWaitEvent(0, ev_join, 0);

    k_agg128<<<nb_agg, 256>>>(b1);
    // layer 2 (fp16 g_hin input, relu pre-applied)
    k_hmma<128, true, 128><<<nt, 256, SMEM128>>>(nullptr, W2, 128);
    k_agg128<<<nb_agg, 256>>>(b2);
    // layer 3 (47 outputs, 48-padded fp16 rows)
    k_hmma<64, true, 48><<<nt, 256, SMEM64>>>(nullptr, W3, 47);
    k_agg47<<<nb_agg, 256>>>(b3, out);
}